// round 3
// baseline (speedup 1.0000x reference)
#include <cuda_runtime.h>
#include <cstdint>

#define H 200
#define S 2047
#define WW 48
#define MID 1023
#define BS 16
#define NCTX 128           // ctx CTAs (16 sentences each)
#define LSTRIDE 26         // padded row stride for sentence weight slice (bank-conflict-free)
#define HSTRIDE 256        // padded (line-aligned) history row
#define SMEM_SENT (400 * LSTRIDE * 16)

// ---------------- scratch (device globals; no allocation) ----------------
// weight sets: 0=ctx 1=tgt 2=prevL0 3=prevL1 4=postL0 5=postL1
__device__ float4 g_Wpack[6][400 * 200];   // [k=0..399][j=0..199] -> rows (j, j+200, j+400, j+600) at col k
__device__ float4 g_bias6[6][200];         // combined bih+bhh per gate
__device__ float  g_sent[S * 200];         // sentence embeddings
__device__ float  g_hist[4][1025 * HSTRIDE]; // per-lane hidden history (h(t) at row t)
__device__ int    g_flag[4][1024];         // per-lane per-step completion counters

__device__ __forceinline__ float sigf(float x) { return 1.0f / (1.0f + __expf(-x)); }

// ---------------- kernel 1: pack weights / biases, zero state ----------------
__global__ void ABHUE_pack_kernel(
    const float* __restrict__ cWih, const float* __restrict__ cWhh,
    const float* __restrict__ cbih, const float* __restrict__ cbhh,
    const float* __restrict__ tWih, const float* __restrict__ tWhh,
    const float* __restrict__ tbih, const float* __restrict__ tbhh,
    const float* __restrict__ pWih, const float* __restrict__ pWhh,
    const float* __restrict__ pbih, const float* __restrict__ pbhh,
    const float* __restrict__ qWih, const float* __restrict__ qWhh,
    const float* __restrict__ qbih, const float* __restrict__ qbhh)
{
    const float* Wih[6] = {cWih, tWih, pWih, pWih + 160000, qWih, qWih + 160000};
    const float* Whh[6] = {cWhh, tWhh, pWhh, pWhh + 160000, qWhh, qWhh + 160000};
    const float* Bih[6] = {cbih, tbih, pbih, pbih + 800,    qbih, qbih + 800};
    const float* Bhh[6] = {cbhh, tbhh, pbhh, pbhh + 800,    qbhh, qbhh + 800};

    int idx = blockIdx.x * blockDim.x + threadIdx.x;
    if (idx < 480000) {
        int set = idx / 80000; int r = idx % 80000;
        int k = r / 200, j = r % 200;
        const float* Wsrc; int kk;
        if (k < 200) { Wsrc = Wih[set]; kk = k; } else { Wsrc = Whh[set]; kk = k - 200; }
        g_Wpack[set][k * 200 + j] = make_float4(
            Wsrc[(j      ) * 200 + kk], Wsrc[(200 + j) * 200 + kk],
            Wsrc[(400 + j) * 200 + kk], Wsrc[(600 + j) * 200 + kk]);
    } else if (idx < 481200) {
        int r = idx - 480000; int set = r / 200; int j = r % 200;
        g_bias6[set][j] = make_float4(
            Bih[set][j      ] + Bhh[set][j      ],
            Bih[set][200 + j] + Bhh[set][200 + j],
            Bih[set][400 + j] + Bhh[set][400 + j],
            Bih[set][600 + j] + Bhh[set][600 + j]);
    } else if (idx < 481200 + 4 * 1024) {
        int r = idx - 481200;
        g_flag[r / 1024][r % 1024] = 0;
    } else if (idx < 481200 + 4 * 1024 + 4 * HSTRIDE) {
        int r = idx - (481200 + 4 * 1024);
        g_hist[r / HSTRIDE][r % HSTRIDE] = 0.0f;   // h(0) = 0 for all 4 lanes
    }
}

// ---------------- kernel 2: word-level batched LSTM (persistent per sentence tile) ----------------
__global__ void __launch_bounds__(224, 1) ABHUE_word_kernel(const float* __restrict__ X)
{
    __shared__ __align__(16) float Xs[BS][200];
    __shared__ __align__(16) float Hs[BS][200];

    const int c = blockIdx.x, tid = threadIdx.x;
    const int set = (c < NCTX) ? 0 : 1;
    const int s0  = (c < NCTX) ? c * BS : MID;
    const int nb  = (c < NCTX) ? ((S - s0 < BS) ? (S - s0) : BS) : 1;
    const float4* __restrict__ Wp = g_Wpack[set];
    const bool act = tid < 200;
    const int j = tid;
    float4 bb = act ? g_bias6[set][j] : make_float4(0.f, 0.f, 0.f, 0.f);

    float cst[BS];
#pragma unroll
    for (int b = 0; b < BS; b++) cst[b] = 0.f;

    for (int i = tid; i < BS * 200; i += 224) ((float*)Hs)[i] = 0.f;
    for (int i = tid; i < BS * 200; i += 224) {
        int b = i / 200, k = i % 200;
        ((float*)Xs)[i] = (b < nb) ? X[(size_t)(s0 + b) * (WW * 200) + k] : 0.f;
    }
    __syncthreads();

    for (int t = 0; t < WW; t++) {
        float ai[BS], af[BS], ag[BS], ao[BS];
        if (act) {
#pragma unroll
            for (int b = 0; b < BS; b++) { ai[b] = bb.x; af[b] = bb.y; ag[b] = bb.z; ao[b] = bb.w; }
            // x contribution (k = 0..199)
#pragma unroll 2
            for (int k4 = 0; k4 < 50; k4++) {
                float4 w0 = Wp[(k4 * 4 + 0) * 200 + j];
                float4 w1 = Wp[(k4 * 4 + 1) * 200 + j];
                float4 w2 = Wp[(k4 * 4 + 2) * 200 + j];
                float4 w3 = Wp[(k4 * 4 + 3) * 200 + j];
#pragma unroll
                for (int b = 0; b < BS; b++) {
                    float4 xv = *(const float4*)(&Xs[b][k4 * 4]);
                    ai[b] = fmaf(w0.x, xv.x, ai[b]); ai[b] = fmaf(w1.x, xv.y, ai[b]);
                    ai[b] = fmaf(w2.x, xv.z, ai[b]); ai[b] = fmaf(w3.x, xv.w, ai[b]);
                    af[b] = fmaf(w0.y, xv.x, af[b]); af[b] = fmaf(w1.y, xv.y, af[b]);
                    af[b] = fmaf(w2.y, xv.z, af[b]); af[b] = fmaf(w3.y, xv.w, af[b]);
                    ag[b] = fmaf(w0.z, xv.x, ag[b]); ag[b] = fmaf(w1.z, xv.y, ag[b]);
                    ag[b] = fmaf(w2.z, xv.z, ag[b]); ag[b] = fmaf(w3.z, xv.w, ag[b]);
                    ao[b] = fmaf(w0.w, xv.x, ao[b]); ao[b] = fmaf(w1.w, xv.y, ao[b]);
                    ao[b] = fmaf(w2.w, xv.z, ao[b]); ao[b] = fmaf(w3.w, xv.w, ao[b]);
                }
            }
            // h contribution (k = 200..399)
#pragma unroll 2
            for (int k4 = 0; k4 < 50; k4++) {
                float4 w0 = Wp[(200 + k4 * 4 + 0) * 200 + j];
                float4 w1 = Wp[(200 + k4 * 4 + 1) * 200 + j];
                float4 w2 = Wp[(200 + k4 * 4 + 2) * 200 + j];
                float4 w3 = Wp[(200 + k4 * 4 + 3) * 200 + j];
#pragma unroll
                for (int b = 0; b < BS; b++) {
                    float4 xv = *(const float4*)(&Hs[b][k4 * 4]);
                    ai[b] = fmaf(w0.x, xv.x, ai[b]); ai[b] = fmaf(w1.x, xv.y, ai[b]);
                    ai[b] = fmaf(w2.x, xv.z, ai[b]); ai[b] = fmaf(w3.x, xv.w, ai[b]);
                    af[b] = fmaf(w0.y, xv.x, af[b]); af[b] = fmaf(w1.y, xv.y, af[b]);
                    af[b] = fmaf(w2.y, xv.z, af[b]); af[b] = fmaf(w3.y, xv.w, af[b]);
                    ag[b] = fmaf(w0.z, xv.x, ag[b]); ag[b] = fmaf(w1.z, xv.y, ag[b]);
                    ag[b] = fmaf(w2.z, xv.z, ag[b]); ag[b] = fmaf(w3.z, xv.w, ag[b]);
                    ao[b] = fmaf(w0.w, xv.x, ao[b]); ao[b] = fmaf(w1.w, xv.y, ao[b]);
                    ao[b] = fmaf(w2.w, xv.z, ao[b]); ao[b] = fmaf(w3.w, xv.w, ao[b]);
                }
            }
        }
        __syncthreads();   // all reads of Xs/Hs complete
        if (act) {
#pragma unroll
            for (int b = 0; b < BS; b++) {
                float iv = sigf(ai[b]), fv = sigf(af[b]);
                float gv = tanhf(ag[b]), ov = sigf(ao[b]);
                cst[b] = fv * cst[b] + iv * gv;
                Hs[b][j] = ov * tanhf(cst[b]);
            }
        }
        if (t < WW - 1) {
            for (int i = tid; i < BS * 200; i += 224) {
                int b = i / 200, k = i % 200;
                ((float*)Xs)[i] = (b < nb) ? X[(size_t)(s0 + b) * (WW * 200) + (t + 1) * 200 + k] : 0.f;
            }
        }
        __syncthreads();   // Hs/Xs ready for next step
    }

    if (act) {
        for (int b = 0; b < nb; b++) {
            int s = s0 + b;
            if (!(c < NCTX && s == MID)) g_sent[s * 200 + j] = Hs[b][j];
        }
    }
}

// ---------------- kernel 3: sentence-level stacked LSTMs (4 pipelined lanes x 8 CTAs) ----------------
__global__ void __launch_bounds__(256, 1) ABHUE_sent_kernel()
{
    extern __shared__ float4 Wsl[];          // [k=0..399][jl padded LSTRIDE]
    __shared__ float xh[400];
    __shared__ float csm[32];

    const int lane = blockIdx.x >> 3;        // 0=prevL0 1=prevL1 2=postL0 3=postL1
    const int rr   = blockIdx.x & 7;
    const int dir  = lane >> 1;
    const int layer = lane & 1;
    const int set  = 2 + lane;
    const int tid  = threadIdx.x;

    for (int idx = tid; idx < 400 * 25; idx += 256) {
        int k = idx / 25, jl = idx % 25;
        Wsl[k * LSTRIDE + jl] = g_Wpack[set][k * 200 + rr * 25 + jl];
    }
    if (tid < 32) csm[tid] = 0.f;

    const int jl = tid >> 3, kp = tid & 7;
    const int jlc = (jl < 25) ? jl : 24;
    const float4 bb = g_bias6[set][rr * 25 + jlc];
    volatile int* ownflag = g_flag[lane];
    volatile int* srcflag = (layer == 1) ? g_flag[lane - 1] : (volatile int*)0;
    float* hist = g_hist[lane];
    const float* histsrc = (layer == 1) ? g_hist[lane - 1] : (const float*)0;
    const unsigned gm = 0xFFu << ((tid & 31) & ~7);
    __syncthreads();

    for (int t = 0; t < 1024; t++) {
        if (tid == 0) {
            if (layer == 1) { while (srcflag[t] < 8) __nanosleep(128); }
            if (t > 0)      { while (ownflag[t - 1] < 8) __nanosleep(128); }
            __threadfence();   // acquire side of release/acquire pair
        }
        __syncthreads();
        // stage x (input, [0..199]) and previous own hidden ([200..399])
        // strided loop — blockDim (256) < 400 staging slots
        for (int i = tid; i < 400; i += 256) {
            float v;
            if (i < 200) {
                if (layer == 0) {
                    int srow = (dir == 0) ? t : (2046 - t);
                    v = g_sent[srow * 200 + i];
                } else {
                    v = __ldcg(&histsrc[(t + 1) * HSTRIDE + i]);
                }
            } else {
                int k = i - 200;
                v = (t == 0) ? 0.f : __ldcg(&hist[t * HSTRIDE + k]);
            }
            xh[i] = v;
        }
        __syncthreads();

        float a0 = 0.f, a1 = 0.f, a2 = 0.f, a3 = 0.f;
#pragma unroll 2
        for (int i = 0; i < 50; i++) {
            int k = kp * 50 + i;
            float4 w = Wsl[k * LSTRIDE + jlc];
            float v = xh[k];
            a0 = fmaf(w.x, v, a0); a1 = fmaf(w.y, v, a1);
            a2 = fmaf(w.z, v, a2); a3 = fmaf(w.w, v, a3);
        }
#pragma unroll
        for (int d = 4; d; d >>= 1) {
            a0 += __shfl_down_sync(gm, a0, d);
            a1 += __shfl_down_sync(gm, a1, d);
            a2 += __shfl_down_sync(gm, a2, d);
            a3 += __shfl_down_sync(gm, a3, d);
        }
        if (kp == 0 && jl < 25) {
            float iv = sigf(a0 + bb.x), fv = sigf(a1 + bb.y);
            float gv = tanhf(a2 + bb.z), ov = sigf(a3 + bb.w);
            float cc = fv * csm[jl] + iv * gv;
            csm[jl] = cc;
            hist[(t + 1) * HSTRIDE + rr * 25 + jl] = ov * tanhf(cc);
            __threadfence();   // release: h-writes visible before flag
        }
        __syncthreads();
        if (tid == 0) atomicAdd((int*)&g_flag[lane][t], 1);
    }
}

// ---------------- kernel 4: final projection ----------------
__global__ void ABHUE_fc_kernel(const float* __restrict__ fcW,
                                const float* __restrict__ fcb,
                                float* __restrict__ out)
{
    int j = threadIdx.x;
    if (j < 200) {
        float s = fcb[j];
        const float* h1 = g_hist[1] + 1024 * HSTRIDE;   // prev top layer final h
        const float* h3 = g_hist[3] + 1024 * HSTRIDE;   // post top layer final h
#pragma unroll 4
        for (int k = 0; k < 200; k++) s = fmaf(fcW[j * 400 + k], h1[k], s);
#pragma unroll 4
        for (int k = 0; k < 200; k++) s = fmaf(fcW[j * 400 + 200 + k], h3[k], s);
        out[j] = s;
    }
}

// ---------------- launch ----------------
extern "C" void kernel_launch(void* const* d_in, const int* in_sizes, int n_in,
                              void* d_out, int out_size)
{
    const float* X     = (const float*)d_in[0];
    const float* cWih  = (const float*)d_in[1];
    const float* cWhh  = (const float*)d_in[2];
    const float* cbih  = (const float*)d_in[3];
    const float* cbhh  = (const float*)d_in[4];
    const float* tWih  = (const float*)d_in[5];
    const float* tWhh  = (const float*)d_in[6];
    const float* tbih  = (const float*)d_in[7];
    const float* tbhh  = (const float*)d_in[8];
    const float* pWih  = (const float*)d_in[9];
    const float* pWhh  = (const float*)d_in[10];
    const float* pbih  = (const float*)d_in[11];
    const float* pbhh  = (const float*)d_in[12];
    const float* qWih  = (const float*)d_in[13];
    const float* qWhh  = (const float*)d_in[14];
    const float* qbih  = (const float*)d_in[15];
    const float* qbhh  = (const float*)d_in[16];
    const float* fcW   = (const float*)d_in[17];
    const float* fcb   = (const float*)d_in[18];

    cudaFuncSetAttribute(ABHUE_sent_kernel,
                         cudaFuncAttributeMaxDynamicSharedMemorySize, SMEM_SENT);

    int total = 481200 + 4 * 1024 + 4 * HSTRIDE;
    int grid = (total + 255) / 256;
    ABHUE_pack_kernel<<<grid, 256>>>(cWih, cWhh, cbih, cbhh,
                                     tWih, tWhh, tbih, tbhh,
                                     pWih, pWhh, pbih, pbhh,
                                     qWih, qWhh, qbih, qbhh);
    ABHUE_word_kernel<<<NCTX + 1, 224>>>(X);
    ABHUE_sent_kernel<<<32, 256, SMEM_SENT>>>();
    ABHUE_fc_kernel<<<1, 256>>>(fcW, fcb, (float*)d_out);
}

// round 5
// speedup vs baseline: 1.2196x; 1.2196x over previous
#include <cuda_runtime.h>
#include <cstdint>

#define H 200
#define S 2047
#define WW 48
#define MID 1023
#define BS 16
#define NCTX 128           // ctx CTAs (16 sentences each)
#define LSTRIDE 26         // padded float4 row stride for sentence weight slice
#define HSTRIDE 256        // padded history row (floats)
#define SMEM_SENT (400 * LSTRIDE * 16)

// ---------------- scratch (device globals; no allocation) ----------------
__device__ float4 g_Wpack2[2][80000];      // word sets (0=ctx,1=tgt): [(pk*2+half)*200 + j]
                                           //   half0=(i_k0,i_k1,f_k0,f_k1) half1=(g_k0,g_k1,o_k0,o_k1)
__device__ float4 g_WpackS[4][80000];      // sent sets (prevL0,prevL1,postL0,postL1): [k*200 + j] = rows(j,j+200,j+400,j+600) col k
__device__ float4 g_bias6[6][200];         // combined bih+bhh; 0=ctx 1=tgt 2..5 = sent sets
__device__ float  g_sent[S * 200];         // sentence embeddings
__device__ float  g_hist[2][1024 * HSTRIDE]; // per-dir L0 hidden history (row t = h0 after step t)
__device__ int    g_flag[2][1024];         // per-dir per-step L0 completion counters
__device__ float  g_final[2 * 256];        // final top-layer h per direction

__device__ __forceinline__ float sigf(float x) { return 1.0f / (1.0f + __expf(-x)); }

struct __align__(16) ULL2 { unsigned long long x, y; };

__device__ __forceinline__ void ffma2(unsigned long long& a, unsigned long long w, unsigned long long x) {
    asm("fma.rn.f32x2 %0, %1, %2, %0;" : "+l"(a) : "l"(w), "l"(x));
}
__device__ __forceinline__ float2 upk2(unsigned long long v) {
    float2 r; asm("mov.b64 {%0,%1}, %2;" : "=f"(r.x), "=f"(r.y) : "l"(v)); return r;
}
__device__ __forceinline__ void st_cluster_f32(uint32_t laddr, int rank, float v) {
    uint32_t ra;
    asm volatile("mapa.shared::cluster.u32 %0, %1, %2;" : "=r"(ra) : "r"(laddr), "r"(rank));
    asm volatile("st.shared::cluster.f32 [%0], %1;" :: "r"(ra), "f"(v) : "memory");
}
#define CLUSTER_SYNC() do { \
    asm volatile("barrier.cluster.arrive.aligned;" ::: "memory"); \
    asm volatile("barrier.cluster.wait.aligned;"   ::: "memory"); } while (0)

// ---------------- kernel 1: pack weights / biases, reset flags ----------------
__global__ void ABHUE_pack_kernel(
    const float* __restrict__ cWih, const float* __restrict__ cWhh,
    const float* __restrict__ cbih, const float* __restrict__ cbhh,
    const float* __restrict__ tWih, const float* __restrict__ tWhh,
    const float* __restrict__ tbih, const float* __restrict__ tbhh,
    const float* __restrict__ pWih, const float* __restrict__ pWhh,
    const float* __restrict__ pbih, const float* __restrict__ pbhh,
    const float* __restrict__ qWih, const float* __restrict__ qWhh,
    const float* __restrict__ qbih, const float* __restrict__ qbhh)
{
    const float* Wih6[6] = {cWih, tWih, pWih, pWih + 160000, qWih, qWih + 160000};
    const float* Whh6[6] = {cWhh, tWhh, pWhh, pWhh + 160000, qWhh, qWhh + 160000};
    const float* Bih6[6] = {cbih, tbih, pbih, pbih + 800,    qbih, qbih + 800};
    const float* Bhh6[6] = {cbhh, tbhh, pbhh, pbhh + 800,    qbhh, qbhh + 800};

    int idx = blockIdx.x * blockDim.x + threadIdx.x;
    if (idx < 160000) {
        // word pairwise layout
        int set = idx / 80000; int r = idx % 80000;
        int j = r % 200; int q = r / 200;       // q = pk*2 + half
        int half = q & 1, pk = q >> 1;
        int k0 = 2 * pk;
        const float* Wsrc; int kk;
        if (k0 < 200) { Wsrc = Wih6[set]; kk = k0; } else { Wsrc = Whh6[set]; kk = k0 - 200; }
        int r0 = (half ? 400 : 0) + j;
        int r1 = r0 + 200;
        g_Wpack2[set][idx % 80000] = make_float4(
            Wsrc[r0 * 200 + kk], Wsrc[r0 * 200 + kk + 1],
            Wsrc[r1 * 200 + kk], Wsrc[r1 * 200 + kk + 1]);
    } else if (idx < 480000) {
        // sentence gate-grouped layout
        int r = idx - 160000;
        int set = r / 80000; r %= 80000;
        int k = r / 200, j = r % 200;
        const float* Wsrc; int kk;
        if (k < 200) { Wsrc = Wih6[2 + set]; kk = k; } else { Wsrc = Whh6[2 + set]; kk = k - 200; }
        g_WpackS[set][(r / 200) * 200 + j] = make_float4(
            Wsrc[(j      ) * 200 + kk], Wsrc[(200 + j) * 200 + kk],
            Wsrc[(400 + j) * 200 + kk], Wsrc[(600 + j) * 200 + kk]);
    } else if (idx < 481200) {
        int r = idx - 480000; int set = r / 200; int j = r % 200;
        g_bias6[set][j] = make_float4(
            Bih6[set][j      ] + Bhh6[set][j      ],
            Bih6[set][200 + j] + Bhh6[set][200 + j],
            Bih6[set][400 + j] + Bhh6[set][400 + j],
            Bih6[set][600 + j] + Bhh6[set][600 + j]);
    } else if (idx < 481200 + 2048) {
        int r = idx - 481200;
        g_flag[r / 1024][r % 1024] = 0;
    }
}

// ---------------- kernel 2: word-level batched LSTM (FFMA2 + weight prefetch) ----------------
__global__ void __launch_bounds__(224, 1) ABHUE_word_kernel(const float* __restrict__ X)
{
    __shared__ __align__(16) float Xs[BS][200];
    __shared__ __align__(16) float Hs[BS][200];

    const int c = blockIdx.x, tid = threadIdx.x;
    const int set = (c < NCTX) ? 0 : 1;
    const int s0  = (c < NCTX) ? c * BS : MID;
    const int nb  = (c < NCTX) ? ((S - s0 < BS) ? (S - s0) : BS) : 1;
    const ULL2* __restrict__ Wp = reinterpret_cast<const ULL2*>(g_Wpack2[set]);
    const bool act = tid < 200;
    const int j = tid;
    float4 bb = act ? g_bias6[set][j] : make_float4(0.f, 0.f, 0.f, 0.f);

    float cst[BS];
#pragma unroll
    for (int b = 0; b < BS; b++) cst[b] = 0.f;

    for (int i = tid; i < BS * 200; i += 224) ((float*)Hs)[i] = 0.f;
    for (int i = tid; i < BS * 200; i += 224) {
        int b = i / 200, k = i % 200;
        ((float*)Xs)[i] = (b < nb) ? X[(size_t)(s0 + b) * (WW * 200) + k] : 0.f;
    }
    __syncthreads();

    const float* bx = &Xs[0][0];
    const float* bh = &Hs[0][0];

    for (int t = 0; t < WW; t++) {
        unsigned long long Ai[BS], Af[BS], Ag[BS], Ao[BS];
        if (act) {
#pragma unroll
            for (int b = 0; b < BS; b++) { Ai[b] = 0ull; Af[b] = 0ull; Ag[b] = 0ull; Ao[b] = 0ull; }
            // preload weights for k4=0
            ULL2 cA0 = Wp[0 * 200 + j], cB0 = Wp[1 * 200 + j];
            ULL2 cA1 = Wp[2 * 200 + j], cB1 = Wp[3 * 200 + j];
#pragma unroll 1
            for (int k4 = 0; k4 < 100; k4++) {
                ULL2 nA0 = cA0, nB0 = cB0, nA1 = cA1, nB1 = cB1;
                if (k4 < 99) {
                    const ULL2* wrow = Wp + (4 * (k4 + 1)) * 200 + j;
                    nA0 = wrow[0];   nB0 = wrow[200];
                    nA1 = wrow[400]; nB1 = wrow[600];
                }
                const float* base = (k4 < 50) ? (bx + 4 * k4) : (bh + (4 * k4 - 200));
#pragma unroll
                for (int b = 0; b < BS; b++) {
                    ULL2 xp = *reinterpret_cast<const ULL2*>(base + b * 200);
                    ffma2(Ai[b], cA0.x, xp.x); ffma2(Af[b], cA0.y, xp.x);
                    ffma2(Ag[b], cB0.x, xp.x); ffma2(Ao[b], cB0.y, xp.x);
                    ffma2(Ai[b], cA1.x, xp.y); ffma2(Af[b], cA1.y, xp.y);
                    ffma2(Ag[b], cB1.x, xp.y); ffma2(Ao[b], cB1.y, xp.y);
                }
                cA0 = nA0; cB0 = nB0; cA1 = nA1; cB1 = nB1;
            }
        }
        __syncthreads();   // all reads of Xs/Hs complete
        if (act) {
#pragma unroll
            for (int b = 0; b < BS; b++) {
                float2 pi = upk2(Ai[b]), pf = upk2(Af[b]);
                float2 pg = upk2(Ag[b]), po = upk2(Ao[b]);
                float iv = sigf(pi.x + pi.y + bb.x);
                float fv = sigf(pf.x + pf.y + bb.y);
                float gv = tanhf(pg.x + pg.y + bb.z);
                float ov = sigf(po.x + po.y + bb.w);
                cst[b] = fv * cst[b] + iv * gv;
                Hs[b][j] = ov * tanhf(cst[b]);
            }
        }
        if (t < WW - 1) {
            for (int i = tid; i < BS * 200; i += 224) {
                int b = i / 200, k = i % 200;
                ((float*)Xs)[i] = (b < nb) ? X[(size_t)(s0 + b) * (WW * 200) + (t + 1) * 200 + k] : 0.f;
            }
        }
        __syncthreads();   // Hs/Xs ready for next step
    }

    if (act) {
        for (int b = 0; b < nb; b++) {
            int s = s0 + b;
            if (!(c < NCTX && s == MID)) g_sent[s * 200 + j] = Hs[b][j];
        }
    }
}

// ---------------- kernel 3: sentence-level LSTMs — 4 clusters x 8 CTAs, DSMEM recurrence ----------------
__global__ void __launch_bounds__(256, 1) __cluster_dims__(8, 1, 1) ABHUE_sent_kernel()
{
    extern __shared__ float4 Wsl[];                 // [k=0..399][jl padded LSTRIDE]
    __shared__ __align__(16) float hbuf[2][200];    // own-layer h, double-buffered by parity
    __shared__ __align__(16) float xbuf[200];       // staged input

    const int cid   = blockIdx.x >> 3;    // 0=prevL0 1=prevL1 2=postL0 3=postL1
    const int rr    = blockIdx.x & 7;
    const int dir   = cid >> 1;
    const int layer = cid & 1;
    const int tid   = threadIdx.x;
    const int jl = tid >> 3, kp = tid & 7;
    const int jlc = (jl < 25) ? jl : 24;
    const bool act = tid < 200;

    for (int idx = tid; idx < 400 * 25; idx += 256) {
        int k = idx / 25, jj = idx % 25;
        Wsl[k * LSTRIDE + jj] = g_WpackS[cid][k * 200 + rr * 25 + jj];
    }
    for (int i = tid; i < 400; i += 256) ((float*)hbuf)[i] = 0.f;

    const float4 bb = g_bias6[2 + cid][rr * 25 + jlc];
    float creg = 0.f;
    volatile int* flg = g_flag[dir];
    float* h0g = g_hist[dir];
    const unsigned gm = 0xFFu << ((tid & 31) & ~7);
    const uint32_t hbase = (uint32_t)__cvta_generic_to_shared(&hbuf[0][0]);
    const uint32_t myoff = (uint32_t)((rr * 25 + jlc) * 4);

    __syncthreads();
    CLUSTER_SYNC();   // all peers zeroed hbuf before any DSMEM write can land

    if (layer == 0) {
        float xreg = 0.f;
        if (act) { int row = dir ? 2046 : 0; xreg = g_sent[row * 200 + tid]; }
        for (int i = 0; i < 1024; i++) {
            const int par = i & 1;
            if (act) xbuf[tid] = xreg;
            __syncthreads();
            if (act && i + 1 < 1024) {
                int row = dir ? (2046 - (i + 1)) : (i + 1);
                xreg = __ldcg(&g_sent[row * 200 + tid]);
            }
            float a0 = 0.f, a1 = 0.f, a2 = 0.f, a3 = 0.f;
            {
                const float* src = (kp < 4) ? xbuf : hbuf[par ^ 1];
                const int kb = (kp & 3) * 50;
#pragma unroll 2
                for (int q = 0; q < 50; q++) {
                    float4 w = Wsl[(kp * 50 + q) * LSTRIDE + jlc];
                    float v = src[kb + q];
                    a0 = fmaf(w.x, v, a0); a1 = fmaf(w.y, v, a1);
                    a2 = fmaf(w.z, v, a2); a3 = fmaf(w.w, v, a3);
                }
            }
#pragma unroll
            for (int d = 4; d; d >>= 1) {
                a0 += __shfl_down_sync(gm, a0, d);
                a1 += __shfl_down_sync(gm, a1, d);
                a2 += __shfl_down_sync(gm, a2, d);
                a3 += __shfl_down_sync(gm, a3, d);
            }
            if (kp == 0 && jl < 25) {
                float iv = sigf(a0 + bb.x), fv = sigf(a1 + bb.y);
                float gv = tanhf(a2 + bb.z), ov = sigf(a3 + bb.w);
                creg = fv * creg + iv * gv;
                float hv = ov * tanhf(creg);
                uint32_t la = hbase + (uint32_t)(par * 800) + myoff;
#pragma unroll
                for (int cta = 0; cta < 8; cta++) st_cluster_f32(la, cta, hv);
                h0g[i * HSTRIDE + rr * 25 + jl] = hv;       // feed layer 1
            }
            __syncthreads();
            if (tid == 0) { __threadfence(); atomicAdd((int*)&g_flag[dir][i], 1); }
            CLUSTER_SYNC();   // DSMEM h(t) visible cluster-wide for next step
        }
    } else {
        float h0reg = 0.f;
        for (int i = 0; i < 1026; i++) {
            const int par = i & 1;
            if (act) xbuf[tid] = h0reg;          // h0(i-2) staged as x for t' = i-2
            __syncthreads();
            if (i >= 1 && i <= 1024) {           // acquire + prefetch h0 row (i-1)
                if (tid == 0) {
                    while (flg[i - 1] < 8) __nanosleep(64);
                    __threadfence();
                }
                __syncthreads();
                if (act) h0reg = __ldcg(&h0g[(i - 1) * HSTRIDE + tid]);
            }
            if (i >= 2) {
                float a0 = 0.f, a1 = 0.f, a2 = 0.f, a3 = 0.f;
                {
                    const float* src = (kp < 4) ? xbuf : hbuf[par ^ 1];
                    const int kb = (kp & 3) * 50;
#pragma unroll 2
                    for (int q = 0; q < 50; q++) {
                        float4 w = Wsl[(kp * 50 + q) * LSTRIDE + jlc];
                        float v = src[kb + q];
                        a0 = fmaf(w.x, v, a0); a1 = fmaf(w.y, v, a1);
                        a2 = fmaf(w.z, v, a2); a3 = fmaf(w.w, v, a3);
                    }
                }
#pragma unroll
                for (int d = 4; d; d >>= 1) {
                    a0 += __shfl_down_sync(gm, a0, d);
                    a1 += __shfl_down_sync(gm, a1, d);
                    a2 += __shfl_down_sync(gm, a2, d);
                    a3 += __shfl_down_sync(gm, a3, d);
                }
                if (kp == 0 && jl < 25) {
                    float iv = sigf(a0 + bb.x), fv = sigf(a1 + bb.y);
                    float gv = tanhf(a2 + bb.z), ov = sigf(a3 + bb.w);
                    creg = fv * creg + iv * gv;
                    float hv = ov * tanhf(creg);
                    uint32_t la = hbase + (uint32_t)(par * 800) + myoff;
#pragma unroll
                    for (int cta = 0; cta < 8; cta++) st_cluster_f32(la, cta, hv);
                    if (i == 1025) g_final[dir * 256 + rr * 25 + jl] = hv;
                }
            }
            CLUSTER_SYNC();
        }
    }
}

// ---------------- kernel 4: final projection (warp per output row) ----------------
__global__ void ABHUE_fc_kernel(const float* __restrict__ fcW,
                                const float* __restrict__ fcb,
                                float* __restrict__ out)
{
    __shared__ float hcat[400];
    int tid = threadIdx.x;
    if (tid < 200) {
        hcat[tid]       = g_final[tid];
        hcat[200 + tid] = g_final[256 + tid];
    }
    __syncthreads();
    int w = tid >> 5, l = tid & 31;
    for (int j = w; j < 200; j += 8) {
        float s = 0.f;
        for (int k = l; k < 400; k += 32) s = fmaf(fcW[j * 400 + k], hcat[k], s);
#pragma unroll
        for (int d = 16; d; d >>= 1) s += __shfl_down_sync(0xFFFFFFFFu, s, d);
        if (l == 0) out[j] = s + fcb[j];
    }
}

// ---------------- launch ----------------
extern "C" void kernel_launch(void* const* d_in, const int* in_sizes, int n_in,
                              void* d_out, int out_size)
{
    const float* X     = (const float*)d_in[0];
    const float* cWih  = (const float*)d_in[1];
    const float* cWhh  = (const float*)d_in[2];
    const float* cbih  = (const float*)d_in[3];
    const float* cbhh  = (const float*)d_in[4];
    const float* tWih  = (const float*)d_in[5];
    const float* tWhh  = (const float*)d_in[6];
    const float* tbih  = (const float*)d_in[7];
    const float* tbhh  = (const float*)d_in[8];
    const float* pWih  = (const float*)d_in[9];
    const float* pWhh  = (const float*)d_in[10];
    const float* pbih  = (const float*)d_in[11];
    const float* pbhh  = (const float*)d_in[12];
    const float* qWih  = (const float*)d_in[13];
    const float* qWhh  = (const float*)d_in[14];
    const float* qbih  = (const float*)d_in[15];
    const float* qbhh  = (const float*)d_in[16];
    const float* fcW   = (const float*)d_in[17];
    const float* fcb   = (const float*)d_in[18];

    cudaFuncSetAttribute(ABHUE_sent_kernel,
                         cudaFuncAttributeMaxDynamicSharedMemorySize, SMEM_SENT);

    int total = 481200 + 2048;
    int grid = (total + 255) / 256;
    ABHUE_pack_kernel<<<grid, 256>>>(cWih, cWhh, cbih, cbhh,
                                     tWih, tWhh, tbih, tbhh,
                                     pWih, pWhh, pbih, pbhh,
                                     qWih, qWhh, qbih, qbhh);
    ABHUE_word_kernel<<<NCTX + 1, 224>>>(X);
    ABHUE_sent_kernel<<<32, 256, SMEM_SENT>>>();
    ABHUE_fc_kernel<<<1, 256>>>(fcW, fcb, (float*)d_out);
}